// round 1
// baseline (speedup 1.0000x reference)
#include <cuda_runtime.h>

#define KCH    32
#define HW     64
#define TSTEPS 100
#define PLANE  4096               // 64*64
#define STATE  (2*KCH*PLANE)      // 262144 floats = 1 MB

// Double-buffered recurrent state. Step t reads g_state[t&1], writes g_state[(t+1)&1].
// t==0 never reads (treated as zeros), so no re-zeroing is needed between graph replays.
__device__ float g_state[2][STATE];

#define ROWS_L 60                 // 32 output rows + 14 halo each side
#define PITCH  65                 // 64 + 1 pad (bank-conflict-free column access)

__global__ __launch_bounds__(256)
void step_kernel(const float* __restrict__ inbound,
                 const float* __restrict__ Wf,
                 const float* __restrict__ bf,
                 const float* __restrict__ Ws,
                 const float* __restrict__ bs,
                 float* __restrict__ out,
                 int t)
{
    __shared__ float P  [ROWS_L * PITCH];   // raw rows -> (in place) row prefix sums
    __shared__ float H9 [ROWS_L * PITCH];   // horizontal 9-wide box sums
    __shared__ float H29[ROWS_L * PITCH];   // horizontal 29-wide box sums
    __shared__ float WfS[KCH];

    const int b    = blockIdx.x;          // 0..127
    const int n    = b >> 6;              // batch
    const int rem  = b & 63;
    const int k    = rem >> 1;            // channel
    const int half = rem & 1;
    const int r0   = half << 5;           // first output row (0 or 32)

    const int tid = threadIdx.x;
    const float* __restrict__ src = g_state[t & 1];
    float*       __restrict__ dst = g_state[(t + 1) & 1];

    if (tid < KCH) WfS[tid] = Wf[k * KCH + tid];

    // ---- Phase 1: load own-channel rows (r0-14 .. r0+45), zero-padded ----
    const float* plane = src + (n * KCH + k) * PLANE;
    for (int idx = tid; idx < ROWS_L * HW; idx += 256) {
        const int j  = idx >> 6;
        const int w  = idx & 63;
        const int gr = r0 - 14 + j;
        float v = 0.f;
        if (t > 0 && gr >= 0 && gr < HW) v = plane[gr * HW + w];
        P[j * PITCH + w] = v;
    }
    __syncthreads();

    // ---- Phase 1b: inclusive row prefix sums, in place (one thread per row) ----
    if (tid < ROWS_L) {
        float acc = 0.f;
        float* row = &P[tid * PITCH];
        #pragma unroll
        for (int w = 0; w < HW; w++) { acc += row[w]; row[w] = acc; }
    }
    __syncthreads();

    // ---- Phase 2: horizontal box sums (widths 9 and 29), zero-padded ends ----
    for (int idx = tid; idx < ROWS_L * HW; idx += 256) {
        const int j = idx >> 6;
        const int w = idx & 63;
        const float* row = &P[j * PITCH];
        const float hi9  = row[(w + 4  > 63) ? 63 : w + 4];
        const float lo9  = (w >= 5)  ? row[w - 5]  : 0.f;
        const float hi29 = row[(w + 14 > 63) ? 63 : w + 14];
        const float lo29 = (w >= 15) ? row[w - 15] : 0.f;
        H9 [j * PITCH + w] = hi9  - lo9;
        H29[j * PITCH + w] = hi29 - lo29;
    }
    __syncthreads();

    // Surround kernel structure: inh everywhere, exc in centered 9x9
    const float bf_k = bf[k];
    const float bs_k = bs[k];
    const float inh  = Ws[k * 841];            // corner value
    const float emin = Ws[k * 841 + 420] - inh; // center (14,29+14) minus inh

    // Each thread owns 8 contiguous pixels of one row
    const int rr = tid >> 3;                 // 0..31  (row within half)
    const int w0 = (tid & 7) << 3;           // 0,8,...,56
    const int g  = r0 + rr;                  // global row
    const int j  = rr + 14;                  // halo-row index of output row

    // ---- feat: 32-channel mix, float4-vectorized, capture own-channel X ----
    float acc[8], xo[8];
    #pragma unroll
    for (int pi = 0; pi < 8; pi++) { acc[pi] = 0.f; xo[pi] = 0.f; }

    if (t > 0) {
        const float4* base = (const float4*)(src + (size_t)n * KCH * PLANE + g * HW + w0);
        #pragma unroll
        for (int i = 0; i < KCH; i++) {
            const float wv = WfS[i];
            const float4 a  = base[i * (PLANE / 4)];
            const float4 bq = base[i * (PLANE / 4) + 1];
            acc[0] += wv * a.x;  acc[1] += wv * a.y;
            acc[2] += wv * a.z;  acc[3] += wv * a.w;
            acc[4] += wv * bq.x; acc[5] += wv * bq.y;
            acc[6] += wv * bq.z; acc[7] += wv * bq.w;
            if (i == k) {
                xo[0] = a.x;  xo[1] = a.y;  xo[2] = a.z;  xo[3] = a.w;
                xo[4] = bq.x; xo[5] = bq.y; xo[6] = bq.z; xo[7] = bq.w;
            }
        }
    }

    // ---- spatial: vertical box sums from smem ----
    float sp[8];
    #pragma unroll
    for (int pi = 0; pi < 8; pi++) {
        const int w = w0 + pi;
        float b9 = 0.f, b29 = 0.f;
        #pragma unroll
        for (int d = -4; d <= 4; d++)  b9  += H9 [(j + d) * PITCH + w];
        #pragma unroll
        for (int d = -14; d <= 14; d++) b29 += H29[(j + d) * PITCH + w];
        sp[pi] = inh * b29 + emin * b9 + bs_k;
    }

    // ---- combine, update, emit ----
    const size_t poff = (size_t)(n * KCH + k) * PLANE + g * HW + w0;
    const float4 i0 = ((const float4*)(inbound + poff))[0];
    const float4 i1 = ((const float4*)(inbound + poff))[1];
    const float inbv[8] = { i0.x, i0.y, i0.z, i0.w, i1.x, i1.y, i1.z, i1.w };

    float xn[8];
    #pragma unroll
    for (int pi = 0; pi < 8; pi++) {
        const float S = 0.5f * inbv[pi] + acc[pi] + bf_k + sp[pi];
        xn[pi] = 0.8f * xo[pi] + 0.2f * fmaxf(S, 0.f);
    }

    float4* dptr = (float4*)(dst + poff);
    dptr[0] = make_float4(xn[0], xn[1], xn[2], xn[3]);
    dptr[1] = make_float4(xn[4], xn[5], xn[6], xn[7]);

    const size_t ooff = ((size_t)(n * TSTEPS + t) * KCH + k) * PLANE + (size_t)g * HW + w0;
    float4* optr = (float4*)(out + ooff);
    optr[0] = make_float4(xn[0], xn[1], xn[2], xn[3]);
    optr[1] = make_float4(xn[4], xn[5], xn[6], xn[7]);
}

extern "C" void kernel_launch(void* const* d_in, const int* in_sizes, int n_in,
                              void* d_out, int out_size)
{
    const float* inbound = (const float*)d_in[0];
    const float* Wf      = (const float*)d_in[1];
    const float* bf      = (const float*)d_in[2];
    const float* Ws      = (const float*)d_in[3];
    const float* bs      = (const float*)d_in[4];
    float* out = (float*)d_out;

    for (int t = 0; t < TSTEPS; t++) {
        step_kernel<<<128, 256>>>(inbound, Wf, bf, Ws, bs, out, t);
    }
}

// round 2
// speedup vs baseline: 1.5405x; 1.5405x over previous
#include <cuda_runtime.h>

#define KCH    32
#define HW     64
#define TSTEPS 100
#define PLANE  4096
#define NCTA   128
#define NTHR   512
#define ROWS_L 60        // 32 output rows + 14 halo each side
#define PITCH  64        // all smem accesses are row-contiguous across lanes -> no conflicts

// Double-buffered recurrent state. Step t reads g_state[t&1], writes g_state[(t+1)&1].
// t==0 writes zeros into smem tiles itself, so no cross-replay zeroing is needed.
__device__ float g_state[2][2 * KCH * PLANE];

// Grid barrier state. gen is monotonic across graph replays (only relative
// comparisons are used); cnt always returns to 0 after each barrier.
__device__ unsigned g_bar_cnt;
__device__ unsigned g_bar_gen;

__device__ __forceinline__ unsigned ld_acq(const unsigned* p) {
    unsigned v;
    asm volatile("ld.acquire.gpu.global.u32 %0, [%1];" : "=r"(v) : "l"(p) : "memory");
    return v;
}
__device__ __forceinline__ void st_rel(unsigned* p, unsigned v) {
    asm volatile("st.release.gpu.global.u32 [%0], %1;" :: "l"(p), "r"(v) : "memory");
}

// Sense-counting grid barrier. Safe: grid (128) <= SM count (148) with 1 CTA/SM,
// so all CTAs are co-resident in wave 1.
__device__ __forceinline__ void grid_barrier() {
    __syncthreads();
    if (threadIdx.x == 0) {
        unsigned gen = ld_acq(&g_bar_gen);
        __threadfence();                       // make this CTA's stores visible
        if (atomicAdd(&g_bar_cnt, 1u) == NCTA - 1) {
            g_bar_cnt = 0;                     // ordered before release below
            st_rel(&g_bar_gen, gen + 1);
        } else {
            while (ld_acq(&g_bar_gen) == gen) { }
        }
    }
    __syncthreads();
}

__global__ void __launch_bounds__(NTHR, 1)
persist_kernel(const float* __restrict__ inbound,
               const float* __restrict__ Wf,
               const float* __restrict__ bf,
               const float* __restrict__ Ws,
               const float* __restrict__ bs,
               float* __restrict__ out)
{
    extern __shared__ float sm[];
    float* R   = sm;                           // raw own-channel rows [60][64]
    float* H29 = R   + ROWS_L * PITCH;         // 29-wide horizontal box sums
    float* H9  = H29 + ROWS_L * PITCH;         // 9-wide horizontal box sums
    float* S   = H9  + ROWS_L * PITCH;         // feat + 0.5*inb + bf  [32][64]
    float* WfS = S   + 32 * PITCH;             // Wf row for this channel

    const int b    = blockIdx.x;               // 0..127
    const int n    = b >> 6;
    const int rem  = b & 63;
    const int k    = rem >> 1;
    const int half = rem & 1;
    const int r0   = half << 5;                // first output row

    const int tid = threadIdx.x;

    if (tid < KCH) WfS[tid] = Wf[k * KCH + tid];
    const float bf_k = bf[k];
    const float bs_k = bs[k];
    const float inh  = Ws[k * 841];                  // uniform inhibition value
    const float emin = Ws[k * 841 + 420] - inh;      // center excitation minus inh

    // ---- feat-phase thread mapping: (row rr_f, 4 contiguous pixels) ----
    const int rr_f = tid >> 4;                 // 0..31
    const int w0_f = (tid & 15) << 2;          // 0,4,...,60
    const int g_f  = r0 + rr_f;
    const size_t plane_off = (size_t)(n * KCH + k) * PLANE;
    const float4 inb4 = *(const float4*)(inbound + plane_off + g_f * HW + w0_f);
    const float base0 = 0.5f * inb4.x + bf_k;
    const float base1 = 0.5f * inb4.y + bf_k;
    const float base2 = 0.5f * inb4.z + bf_k;
    const float base3 = 0.5f * inb4.w + bf_k;

    // ---- H-phase thread mapping: (halo row j_h, 8-pixel segment) ----
    const int j_h = tid >> 3;                  // 0..63 (only <60 active)
    const int s_h = (tid & 7) << 3;            // 0,8,...,56

    // ---- V-phase thread mapping: (column w_v, 4-row segment) ----
    const int w_v = tid & 63;
    const int seg = tid >> 6;                  // 0..7
    const int rr0 = seg << 2;                  // first output row of segment

    __syncthreads();

    for (int t = 0; t < TSTEPS; t++) {
        const float* __restrict__ src = g_state[t & 1];
        float*       __restrict__ dst = g_state[(t + 1) & 1];

        // ================= Phase L: raw halo rows + feat =================
        {
            const float* plane = src + plane_off;
            #pragma unroll
            for (int it = 0; it < 2; it++) {           // 960 float4s / 512 threads
                int idx = tid + it * NTHR;
                if (idx < ROWS_L * 16) {
                    int j  = idx >> 4;
                    int wq = (idx & 15) << 2;
                    int gr = r0 - 14 + j;
                    float4 v = make_float4(0.f, 0.f, 0.f, 0.f);
                    if (t > 0 && gr >= 0 && gr < HW)
                        v = *(const float4*)(plane + gr * HW + wq);
                    *(float4*)&R[j * PITCH + wq] = v;
                }
            }

            float a0 = 0.f, a1 = 0.f, a2 = 0.f, a3 = 0.f;
            if (t > 0) {
                const float4* bp = (const float4*)(src + (size_t)n * KCH * PLANE
                                                   + g_f * HW + w0_f);
                #pragma unroll
                for (int i = 0; i < KCH; i++) {
                    const float wv = WfS[i];
                    const float4 x = bp[i * (PLANE / 4)];
                    a0 += wv * x.x; a1 += wv * x.y;
                    a2 += wv * x.z; a3 += wv * x.w;
                }
            }
            float* sp_ = &S[rr_f * PITCH + w0_f];
            sp_[0] = base0 + a0; sp_[1] = base1 + a1;
            sp_[2] = base2 + a2; sp_[3] = base3 + a3;
        }
        __syncthreads();

        // ============ Phase H: horizontal box sums (sliding windows) ============
        if (j_h < ROWS_L) {
            float v[36];
            const float* row = &R[j_h * PITCH];
            #pragma unroll
            for (int d = 0; d < 36; d++) {
                int w = s_h - 14 + d;
                v[d] = (w >= 0 && w < HW) ? row[w] : 0.f;
            }
            float s29 = 0.f;
            #pragma unroll
            for (int d = 0; d < 29; d++) s29 += v[d];
            H29[j_h * PITCH + s_h] = s29;
            #pragma unroll
            for (int p = 1; p < 8; p++) {
                s29 += v[p + 28] - v[p - 1];
                H29[j_h * PITCH + s_h + p] = s29;
            }
            float s9 = 0.f;
            #pragma unroll
            for (int d = 10; d < 19; d++) s9 += v[d];
            H9[j_h * PITCH + s_h] = s9;
            #pragma unroll
            for (int p = 1; p < 8; p++) {
                s9 += v[p + 18] - v[p + 9];
                H9[j_h * PITCH + s_h + p] = s9;
            }
        }
        __syncthreads();

        // ============ Phase V: vertical sliding windows + combine + emit ============
        {
            float b29 = 0.f;
            #pragma unroll
            for (int d = 0; d < 29; d++) b29 += H29[(rr0 + d) * PITCH + w_v];
            float b9 = 0.f;
            #pragma unroll
            for (int d = 0; d < 9; d++)  b9  += H9[(rr0 + 10 + d) * PITCH + w_v];

            const size_t out_base = ((size_t)(n * TSTEPS + t) * KCH + k) * PLANE;
            #pragma unroll
            for (int r = 0; r < 4; r++) {
                const int rr = rr0 + r;        // row within half (0..31)
                const int j  = rr + 14;        // halo-row index
                if (r > 0) {
                    b29 += H29[(rr + 28) * PITCH + w_v] - H29[(rr - 1) * PITCH + w_v];
                    b9  += H9 [(j + 4)  * PITCH + w_v] - H9 [(j - 5)  * PITCH + w_v];
                }
                const float sp = inh * b29 + emin * b9 + bs_k;
                const float Sv = S[rr * PITCH + w_v];
                const float xo = R[j * PITCH + w_v];
                const float xn = 0.8f * xo + 0.2f * fmaxf(Sv + sp, 0.f);

                const size_t off = plane_off + (size_t)(r0 + rr) * HW + w_v;
                dst[off] = xn;
                out[out_base + (size_t)(r0 + rr) * HW + w_v] = xn;
            }
        }

        if (t != TSTEPS - 1) grid_barrier();
    }
}

extern "C" void kernel_launch(void* const* d_in, const int* in_sizes, int n_in,
                              void* d_out, int out_size)
{
    const float* inbound = (const float*)d_in[0];
    const float* Wf      = (const float*)d_in[1];
    const float* bf      = (const float*)d_in[2];
    const float* Ws      = (const float*)d_in[3];
    const float* bs      = (const float*)d_in[4];
    float* out = (float*)d_out;

    const int smem_bytes = (3 * ROWS_L * PITCH + 32 * PITCH + 32) * sizeof(float);
    static bool attr_set = false;
    if (!attr_set) {
        cudaFuncSetAttribute(persist_kernel,
                             cudaFuncAttributeMaxDynamicSharedMemorySize, smem_bytes);
        attr_set = true;
    }
    persist_kernel<<<NCTA, NTHR, smem_bytes>>>(inbound, Wf, bf, Ws, bs, out);
}

// round 3
// speedup vs baseline: 1.9344x; 1.2558x over previous
#include <cuda_runtime.h>

#define KCH    32
#define HW     64
#define TSTEPS 100
#define PLANE  4096
#define NCTA   128
#define NTHR   512
#define ROWS_L 60        // 32 output rows + 14 halo each side
#define RPITCH 65        // odd pitch: 2-way worst-case conflicts in H phase
#define SPITCH 64        // S tile pitch (float4-aligned, conflict-free reads)

// Double-buffered recurrent state. Step t reads g_state[t&1], writes g_state[(t+1)&1].
__device__ float g_state[2][2 * KCH * PLANE];

// Split grid barrier + per-CTA step flags. All counters are monotonic across
// graph replays; only relative (base-offset) comparisons are used.
__device__ unsigned g_bar_cnt;
__device__ unsigned g_bar_gen;
__device__ unsigned g_flags[NCTA];

__device__ __forceinline__ unsigned ld_acq(const unsigned* p) {
    unsigned v;
    asm volatile("ld.acquire.gpu.global.u32 %0, [%1];" : "=r"(v) : "l"(p) : "memory");
    return v;
}
__device__ __forceinline__ void st_rel(unsigned* p, unsigned v) {
    asm volatile("st.release.gpu.global.u32 [%0], %1;" :: "l"(p), "r"(v) : "memory");
}

__global__ void __launch_bounds__(NTHR, 1)
persist_kernel(const float* __restrict__ inbound,
               const float* __restrict__ Wf,
               const float* __restrict__ bf,
               const float* __restrict__ Ws,
               const float* __restrict__ bs,
               float* __restrict__ out)
{
    extern __shared__ float sm[];
    float* R    = sm;                         // [60][65] raw own-channel halo rows
    float* H29  = R   + ROWS_L * RPITCH;      // [60][65] 29-wide horizontal box sums
    float* H9   = H29 + ROWS_L * RPITCH;      // [60][65] 9-wide horizontal box sums
    float* S    = H9  + ROWS_L * RPITCH;      // [32][64] feat + 0.5*inb + bf
    float* WfS  = S   + 32 * SPITCH;          // Wf row for this channel
    unsigned* uGen0 = (unsigned*)(WfS + KCH);

    const int b    = blockIdx.x;              // 0..127
    const int n    = b >> 6;
    const int rem  = b & 63;
    const int k    = rem >> 1;
    const int half = rem & 1;
    const int r0   = half << 5;
    const int partner = b ^ 1;                // same (n,k), other half

    const int tid = threadIdx.x;

    if (tid < KCH) WfS[tid] = Wf[k * KCH + tid];
    if (tid == 0)  *uGen0 = ld_acq(&g_bar_gen);

    // zero R, H29, H9 (contiguous) — step 0 state is zeros
    for (int i = tid; i < 3 * ROWS_L * RPITCH; i += NTHR) sm[i] = 0.f;

    const float bf_k = bf[k];
    const float bs_k = bs[k];
    const float inh  = Ws[k * 841];                 // uniform inhibition value
    const float emin = Ws[k * 841 + 420] - inh;     // center excitation minus inh

    // ---- feat-phase mapping: (row rr_f, 4 contiguous pixels) ----
    const int rr_f = tid >> 4;                // 0..31
    const int w0_f = (tid & 15) << 2;         // 0,4,...,60
    const int g_f  = r0 + rr_f;
    const size_t plane_off = (size_t)(n * KCH + k) * PLANE;
    const float4 inb4 = *(const float4*)(inbound + plane_off + g_f * HW + w0_f);
    const float base0 = 0.5f * inb4.x + bf_k;
    const float base1 = 0.5f * inb4.y + bf_k;
    const float base2 = 0.5f * inb4.z + bf_k;
    const float base3 = 0.5f * inb4.w + bf_k;

    // S starts as pure base (feat(0) = 0 since X0 = 0)
    *(float4*)&S[rr_f * SPITCH + w0_f] = make_float4(base0, base1, base2, base3);

    // ---- H-phase mapping: (halo row j_h, 8-pixel segment) ----
    const int j_h = tid >> 3;                 // 0..63 (only <60 active)
    const int s_h = (tid & 7) << 3;

    // ---- V-phase mapping: 256 active threads, (column, 8-row segment) ----
    const int w_v  = tid & 63;
    const int sg_v = tid >> 6;                // 0..7; only 0..3 active
    const int rb_v = sg_v << 3;

    __syncthreads();
    const unsigned gen0 = *uGen0;

    for (int t = 0; t < TSTEPS; t++) {
        // ================= feat (t>0): 32-channel mix into S =================
        if (t > 0) {
            const float4* bp = (const float4*)(g_state[t & 1]
                               + (size_t)n * KCH * PLANE + g_f * HW + w0_f);
            float a0 = 0.f, a1 = 0.f, a2 = 0.f, a3 = 0.f;
            #pragma unroll
            for (int i = 0; i < KCH; i++) {
                const float wv = WfS[i];
                const float4 x = bp[i * (PLANE / 4)];
                a0 += wv * x.x; a1 += wv * x.y;
                a2 += wv * x.z; a3 += wv * x.w;
            }
            *(float4*)&S[rr_f * SPITCH + w0_f] =
                make_float4(base0 + a0, base1 + a1, base2 + a2, base3 + a3);
            __syncthreads();
        }

        // ========== V phase: vertical sliding box sums + combine + emit ==========
        if (sg_v < 4) {
            float b29 = 0.f, b9 = 0.f;
            #pragma unroll
            for (int d = 0; d < 29; d++) b29 += H29[(rb_v + d) * RPITCH + w_v];
            #pragma unroll
            for (int d = 0; d < 9;  d++) b9  += H9 [(rb_v + 10 + d) * RPITCH + w_v];

            float* dst = g_state[(t + 1) & 1];
            const size_t out_base = ((size_t)(n * TSTEPS + t) * KCH + k) * PLANE;
            #pragma unroll
            for (int r = 0; r < 8; r++) {
                const int rr = rb_v + r;
                const int j  = rr + 14;
                if (r > 0) {
                    b29 += H29[(rr + 28) * RPITCH + w_v] - H29[(rr - 1) * RPITCH + w_v];
                    b9  += H9 [(j + 4)  * RPITCH + w_v] - H9 [(j - 5)  * RPITCH + w_v];
                }
                const float sp = inh * b29 + emin * b9 + bs_k;
                const float Sv = S[rr * SPITCH + w_v];
                const float xo = R[j * RPITCH + w_v];
                const float xn = 0.8f * xo + 0.2f * fmaxf(Sv + sp, 0.f);

                dst[plane_off + (size_t)(r0 + rr) * HW + w_v] = xn;
                out[out_base  + (size_t)(r0 + rr) * HW + w_v] = xn;
            }
        }
        if (t == TSTEPS - 1) break;

        __syncthreads();                       // all V reads of R/H/S done, dst stored
        const unsigned target = gen0 + (unsigned)t + 1u;
        if (tid == 0) {
            __threadfence();                   // publish this CTA's dst stores
            st_rel(&g_flags[b], target);       // partner handshake flag
            unsigned prev = atomicAdd(&g_bar_cnt, 1u);      // barrier ARRIVE
            if (prev == NCTA - 1) {
                g_bar_cnt = 0;                 // ordered before release below
                st_rel(&g_bar_gen, target);
            }
            // wait only for the partner before touching halo rows
            while ((int)(ld_acq(&g_flags[partner]) - target) < 0) { }
        }
        __syncthreads();

        // ============ halo load for step t+1 (own channel, both halves) ============
        {
            const float* plane = g_state[(t + 1) & 1] + plane_off;
            #pragma unroll
            for (int it = 0; it < 2; it++) {
                int idx = tid + it * NTHR;
                if (idx < ROWS_L * 16) {
                    int j  = idx >> 4;
                    int wq = (idx & 15) << 2;
                    int gr = r0 - 14 + j;
                    float4 v = make_float4(0.f, 0.f, 0.f, 0.f);
                    if (gr >= 0 && gr < HW)
                        v = *(const float4*)(plane + gr * HW + wq);
                    float* rp = &R[j * RPITCH + wq];
                    rp[0] = v.x; rp[1] = v.y; rp[2] = v.z; rp[3] = v.w;
                }
            }
        }
        __syncthreads();

        // ============ H phase: horizontal box sums (register sliding windows) ============
        if (j_h < ROWS_L) {
            float v[36];
            const float* row = &R[j_h * RPITCH];
            #pragma unroll
            for (int d = 0; d < 36; d++) {
                int w = s_h - 14 + d;
                v[d] = (w >= 0 && w < HW) ? row[w] : 0.f;
            }
            float s29 = 0.f;
            #pragma unroll
            for (int d = 0; d < 29; d++) s29 += v[d];
            H29[j_h * RPITCH + s_h] = s29;
            #pragma unroll
            for (int p = 1; p < 8; p++) {
                s29 += v[p + 28] - v[p - 1];
                H29[j_h * RPITCH + s_h + p] = s29;
            }
            float s9 = 0.f;
            #pragma unroll
            for (int d = 10; d < 19; d++) s9 += v[d];
            H9[j_h * RPITCH + s_h] = s9;
            #pragma unroll
            for (int p = 1; p < 8; p++) {
                s9 += v[p + 18] - v[p + 9];
                H9[j_h * RPITCH + s_h + p] = s9;
            }
        }

        // barrier WAIT (mostly already satisfied — hidden behind halo + H work)
        if (tid == 0) {
            while ((int)(ld_acq(&g_bar_gen) - target) < 0) { }
        }
        __syncthreads();
    }
}

extern "C" void kernel_launch(void* const* d_in, const int* in_sizes, int n_in,
                              void* d_out, int out_size)
{
    const float* inbound = (const float*)d_in[0];
    const float* Wf      = (const float*)d_in[1];
    const float* bf      = (const float*)d_in[2];
    const float* Ws      = (const float*)d_in[3];
    const float* bs      = (const float*)d_in[4];
    float* out = (float*)d_out;

    const int smem_bytes = (3 * ROWS_L * RPITCH + 32 * SPITCH + KCH + 8) * sizeof(float);
    static bool attr_set = false;
    if (!attr_set) {
        cudaFuncSetAttribute(persist_kernel,
                             cudaFuncAttributeMaxDynamicSharedMemorySize, smem_bytes);
        attr_set = true;
    }
    persist_kernel<<<NCTA, NTHR, smem_bytes>>>(inbound, Wf, bf, Ws, bs, out);
}